// round 11
// baseline (speedup 1.0000x reference)
#include <cuda_runtime.h>
#include <cuda_bf16.h>
#include <math.h>

// Problem dims (fixed by the reference)
#define B_SZ 1024
#define D_SZ 2048
#define N_SZ 30000

// GEMM tiling
#define BM 128
#define BN 128
#define BK 16
#define TM 8
#define TN 8
// threads per block = (BM/TM)*(BN/TN) = 16*16 = 256

// Scratch for the memory-bank update argmax.
// -2 = row untouched, -1 = touched but no update_flag, >=0 = last updating step index.
__device__ int g_winner[N_SZ];

// ---------------------------------------------------------------------------
// Kernel 1: init winner array
// ---------------------------------------------------------------------------
__global__ void init_winner_kernel() {
    int i = blockIdx.x * blockDim.x + threadIdx.x;
    if (i < N_SZ) g_winner[i] = -2;
}

// ---------------------------------------------------------------------------
// Kernel 2: mark touched rows / find last updating step per row.
// NOTE: indexes is int32 (JAX x64 is disabled; jnp.int64 request silently
// downcasts to int32). atomicMax is commutative -> deterministic.
// ---------------------------------------------------------------------------
__global__ void mark_kernel(const int* __restrict__ indexes,
                            const int* __restrict__ update_flag) {
    int i = blockIdx.x * blockDim.x + threadIdx.x;
    if (i < B_SZ) {
        int y = indexes[i];
        int v = (update_flag[i] > 0) ? i : -1;
        if (y >= 0 && y < N_SZ) atomicMax(&g_winner[y], v);
    }
}

// ---------------------------------------------------------------------------
// Kernel 3: produce new_features. One block (256 threads) per row.
//   winner == -2 : copy original row
//   winner == -1 : normalize original row
//   winner >=  0 : normalize inputs[winner]
// ---------------------------------------------------------------------------
__global__ void update_rows_kernel(const float* __restrict__ inputs,
                                   const float* __restrict__ feats,
                                   float* __restrict__ out_feats) {
    int y = blockIdx.x;
    int t = threadIdx.x;            // 0..255, each handles 8 floats (2 x float4)
    int w = g_winner[y];

    const float* src = (w >= 0) ? (inputs + (size_t)w * D_SZ)
                                : (feats  + (size_t)y * D_SZ);
    float* dst = out_feats + (size_t)y * D_SZ;

    float4 v0 = *reinterpret_cast<const float4*>(src + t * 4);
    float4 v1 = *reinterpret_cast<const float4*>(src + 1024 + t * 4);

    if (w == -2) {  // untouched: plain copy (uniform branch across block)
        *reinterpret_cast<float4*>(dst + t * 4)        = v0;
        *reinterpret_cast<float4*>(dst + 1024 + t * 4) = v1;
        return;
    }

    float ss = v0.x * v0.x + v0.y * v0.y + v0.z * v0.z + v0.w * v0.w
             + v1.x * v1.x + v1.y * v1.y + v1.z * v1.z + v1.w * v1.w;

    // block reduction: warp shuffle then cross-warp via smem
    #pragma unroll
    for (int o = 16; o > 0; o >>= 1)
        ss += __shfl_xor_sync(0xffffffffu, ss, o);

    __shared__ float sred[8];
    __shared__ float stot;
    if ((t & 31) == 0) sred[t >> 5] = ss;
    __syncthreads();
    if (t < 8) {
        float v = sred[t];
        v += __shfl_xor_sync(0x000000ffu, v, 4);
        v += __shfl_xor_sync(0x000000ffu, v, 2);
        v += __shfl_xor_sync(0x000000ffu, v, 1);
        if (t == 0) stot = v;
    }
    __syncthreads();

    float inv = 1.0f / fmaxf(sqrtf(stot), 1e-12f);

    v0.x *= inv; v0.y *= inv; v0.z *= inv; v0.w *= inv;
    v1.x *= inv; v1.y *= inv; v1.z *= inv; v1.w *= inv;
    *reinterpret_cast<float4*>(dst + t * 4)        = v0;
    *reinterpret_cast<float4*>(dst + 1024 + t * 4) = v1;
}

// ---------------------------------------------------------------------------
// Kernel 4: SGEMM  C[b][n] = sum_k A[b][k] * F[n][k]
// A: [B_SZ, D_SZ] row-major, F: [N_SZ, D_SZ] row-major (so this is A @ F^T).
// 128x128 tile, BK=16, 256 threads, 8x8 accumulators per thread.
// ---------------------------------------------------------------------------
__global__ __launch_bounds__(256, 2)
void sgemm_kernel(const float* __restrict__ A,
                  const float* __restrict__ F,
                  float* __restrict__ C) {
    __shared__ __align__(16) float As[BK][BM];
    __shared__ __align__(16) float Bs[BK][BN];

    const int n0 = blockIdx.x * BN;   // column tile (over N)
    const int m0 = blockIdx.y * BM;   // row tile (over B)

    const int tid = threadIdx.x;
    const int tr  = tid >> 4;         // 0..15
    const int tc  = tid & 15;         // 0..15

    // cooperative load mapping: 128 rows x 4 float4 per row = 512 float4;
    // 256 threads -> 2 float4 each (row groups 0..63 and 64..127)
    const int lrow = tid >> 2;            // 0..63
    const int lcol = (tid & 3) << 2;      // 0,4,8,12 (float offset within BK)

    float acc[TM][TN];
    #pragma unroll
    for (int i = 0; i < TM; i++)
        #pragma unroll
        for (int j = 0; j < TN; j++)
            acc[i][j] = 0.0f;

    const float* Abase = A + (size_t)m0 * D_SZ;
    const float* Fbase = F + (size_t)n0 * D_SZ;

    for (int k0 = 0; k0 < D_SZ; k0 += BK) {
        // --- load A tile (B rows always in-bounds: B_SZ % BM == 0) ---
        #pragma unroll
        for (int s = 0; s < 2; s++) {
            int row = lrow + s * 64;
            float4 a = *reinterpret_cast<const float4*>(
                Abase + (size_t)row * D_SZ + k0 + lcol);
            As[lcol + 0][row] = a.x;
            As[lcol + 1][row] = a.y;
            As[lcol + 2][row] = a.z;
            As[lcol + 3][row] = a.w;
        }
        // --- load F tile (guard N edge) ---
        #pragma unroll
        for (int s = 0; s < 2; s++) {
            int row = lrow + s * 64;
            float4 b;
            if (n0 + row < N_SZ) {
                b = *reinterpret_cast<const float4*>(
                    Fbase + (size_t)row * D_SZ + k0 + lcol);
            } else {
                b = make_float4(0.f, 0.f, 0.f, 0.f);
            }
            Bs[lcol + 0][row] = b.x;
            Bs[lcol + 1][row] = b.y;
            Bs[lcol + 2][row] = b.z;
            Bs[lcol + 3][row] = b.w;
        }
        __syncthreads();

        #pragma unroll
        for (int k = 0; k < BK; k++) {
            float ra[TM], rb[TN];
            float4 a0 = *reinterpret_cast<const float4*>(&As[k][tr * TM]);
            float4 a1 = *reinterpret_cast<const float4*>(&As[k][tr * TM + 4]);
            float4 b0 = *reinterpret_cast<const float4*>(&Bs[k][tc * TN]);
            float4 b1 = *reinterpret_cast<const float4*>(&Bs[k][tc * TN + 4]);
            ra[0]=a0.x; ra[1]=a0.y; ra[2]=a0.z; ra[3]=a0.w;
            ra[4]=a1.x; ra[5]=a1.y; ra[6]=a1.z; ra[7]=a1.w;
            rb[0]=b0.x; rb[1]=b0.y; rb[2]=b0.z; rb[3]=b0.w;
            rb[4]=b1.x; rb[5]=b1.y; rb[6]=b1.z; rb[7]=b1.w;
            #pragma unroll
            for (int i = 0; i < TM; i++)
                #pragma unroll
                for (int j = 0; j < TN; j++)
                    acc[i][j] = fmaf(ra[i], rb[j], acc[i][j]);
        }
        __syncthreads();
    }

    // --- store (guard N edge; B edge never triggers) ---
    const int cbase = n0 + tc * TN;
    #pragma unroll
    for (int i = 0; i < TM; i++) {
        size_t m = (size_t)(m0 + tr * TM + i);
        float* Crow = C + m * (size_t)N_SZ + cbase;
        #pragma unroll
        for (int j = 0; j < TN; j++) {
            if (cbase + j < N_SZ) Crow[j] = acc[i][j];
        }
    }
}

// ---------------------------------------------------------------------------
// Launch. Inputs (metadata order): inputs f32[B,D], features f32[N,D],
// IoU f32[B] (unused by max_iou path), indexes int32[B] (JAX x64 disabled),
// update_flag int32[B].
// Output: concat( outputs f32[B,N], new_features f32[N,D] ).
// ---------------------------------------------------------------------------
extern "C" void kernel_launch(void* const* d_in, const int* in_sizes, int n_in,
                              void* d_out, int out_size) {
    const float* inputs      = (const float*)d_in[0];
    const float* features    = (const float*)d_in[1];
    // d_in[2] = IoU, unused (max_iou update ignores clamped IoU)
    const int*   indexes     = (const int*)d_in[3];   // int32, NOT int64
    const int*   update_flag = (const int*)d_in[4];

    float* out         = (float*)d_out;                    // [B, N]
    float* out_feats   = out + (size_t)B_SZ * N_SZ;        // [N, D]

    // GEMM (dominant cost) first
    dim3 ggrid((N_SZ + BN - 1) / BN, B_SZ / BM);
    sgemm_kernel<<<ggrid, 256>>>(inputs, features, out);

    // Memory-bank update pipeline
    init_winner_kernel<<<(N_SZ + 255) / 256, 256>>>();
    mark_kernel<<<(B_SZ + 255) / 256, 256>>>(indexes, update_flag);
    update_rows_kernel<<<N_SZ, 256>>>(inputs, features, out_feats);
}

// round 14
// speedup vs baseline: 2.3218x; 2.3218x over previous
#include <cuda_runtime.h>
#include <cuda_bf16.h>
#include <math.h>
#include <stdint.h>

// Problem dims (fixed by the reference)
#define B_SZ 1024
#define D_SZ 2048
#define N_SZ 30000

// ---------------------------------------------------------------------------
// Scratch (static __device__ arrays — allowed; no dynamic allocation)
// ---------------------------------------------------------------------------
__device__ int g_winner[N_SZ];
__device__ __nv_bfloat16 g_Ahi[B_SZ * D_SZ];
__device__ __nv_bfloat16 g_Alo[B_SZ * D_SZ];
__device__ __nv_bfloat16 g_Fhi[(size_t)N_SZ * D_SZ];
__device__ __nv_bfloat16 g_Flo[(size_t)N_SZ * D_SZ];

// ---------------------------------------------------------------------------
// PTX helpers — ONLY base-sm_103-legal instructions (sm_80-era):
// mma.sync bf16, ldmatrix, cp.async. No tcgen05 (toolchain targets sm_103).
// ---------------------------------------------------------------------------
__device__ __forceinline__ uint32_t smem_u32(const void* p) {
    uint32_t a;
    asm("{ .reg .u64 t; cvta.to.shared.u64 t, %1; cvt.u32.u64 %0, t; }"
        : "=r"(a) : "l"(p));
    return a;
}

#define LDSM_X4(r, addr) \
    asm volatile("ldmatrix.sync.aligned.m8n8.x4.shared.b16 {%0,%1,%2,%3}, [%4];" \
        : "=r"((r)[0]), "=r"((r)[1]), "=r"((r)[2]), "=r"((r)[3]) : "r"(addr))

#define MMA_BF16(d, a, b) \
    asm volatile("mma.sync.aligned.m16n8k16.row.col.f32.bf16.bf16.f32 " \
        "{%0,%1,%2,%3}, {%4,%5,%6,%7}, {%8,%9}, {%0,%1,%2,%3};" \
        : "+f"((d)[0]), "+f"((d)[1]), "+f"((d)[2]), "+f"((d)[3]) \
        : "r"((a)[0]), "r"((a)[1]), "r"((a)[2]), "r"((a)[3]), \
          "r"((b)[0]), "r"((b)[1]))

#define CP_ASYNC_16(daddr, gptr, nbytes) \
    asm volatile("cp.async.cg.shared.global [%0], [%1], 16, %2;" \
        :: "r"(daddr), "l"(gptr), "r"(nbytes) : "memory")
#define CP_ASYNC_COMMIT() asm volatile("cp.async.commit_group;" ::: "memory")
#define CP_ASYNC_WAIT_ALL() asm volatile("cp.async.wait_group 0;" ::: "memory")

// ---------------------------------------------------------------------------
// Kernel: fp32 -> (hi, lo) bf16 split for A and F
// ---------------------------------------------------------------------------
__global__ void convert_split_kernel(const float* __restrict__ A,
                                     const float* __restrict__ F) {
    const size_t a4 = (size_t)B_SZ * D_SZ / 4;
    const size_t f4 = (size_t)N_SZ * D_SZ / 4;
    size_t i = (size_t)blockIdx.x * blockDim.x + threadIdx.x;
    if (i >= a4 + f4) return;

    const float4* src;
    __nv_bfloat16 *hi_base, *lo_base;
    size_t j;
    if (i < a4) { src = (const float4*)A; hi_base = g_Ahi; lo_base = g_Alo; j = i; }
    else        { src = (const float4*)F; hi_base = g_Fhi; lo_base = g_Flo; j = i - a4; }

    float4 v = src[j];
    __nv_bfloat16 h0 = __float2bfloat16(v.x);
    __nv_bfloat16 h1 = __float2bfloat16(v.y);
    __nv_bfloat16 h2 = __float2bfloat16(v.z);
    __nv_bfloat16 h3 = __float2bfloat16(v.w);
    __nv_bfloat16 l0 = __float2bfloat16(v.x - __bfloat162float(h0));
    __nv_bfloat16 l1 = __float2bfloat16(v.y - __bfloat162float(h1));
    __nv_bfloat16 l2 = __float2bfloat16(v.z - __bfloat162float(h2));
    __nv_bfloat16 l3 = __float2bfloat16(v.w - __bfloat162float(h3));

    ushort4 hp, lp;
    hp.x = __bfloat16_as_ushort(h0); hp.y = __bfloat16_as_ushort(h1);
    hp.z = __bfloat16_as_ushort(h2); hp.w = __bfloat16_as_ushort(h3);
    lp.x = __bfloat16_as_ushort(l0); lp.y = __bfloat16_as_ushort(l1);
    lp.z = __bfloat16_as_ushort(l2); lp.w = __bfloat16_as_ushort(l3);
    *reinterpret_cast<ushort4*>(hi_base + 4 * j) = hp;
    *reinterpret_cast<ushort4*>(lo_base + 4 * j) = lp;
}

// ---------------------------------------------------------------------------
// HMMA GEMM:  C[m][n] = sum_k A[m][k] * F[n][k]  via 3-term bf16 split
// (hi*hi + hi*lo + lo*hi; dropped lo*lo ~ 2^-18 relative).
// Tile 128x128, BK=32, 256 threads = 8 warps (2M x 4N), warp tile 64x32,
// m16n8k16 fragments. Double-buffered cp.async pipeline.
// Both A and B tiles are K-contiguous => BOTH use non-trans ldmatrix
// (row.col mma: B frag = {B[k][n], B[k+1][n]} per lane = k-pair of one n-row).
// SMEM per stage: 4 arrays (Ahi,Alo,Fhi,Flo) x [128 rows][40 bf16] (80B pad
// => ldmatrix row addrs hit banks 20r mod 32: all distinct, conflict-free).
// ---------------------------------------------------------------------------
#define BK 32
#define ROW_B 80
#define ARR_BYTES (128 * ROW_B)          // 10240
#define STAGE_BYTES (4 * ARR_BYTES)      // 40960
#define SMEM_DYN (2 * STAGE_BYTES)       // 81920

__device__ __forceinline__ void issue_tile_loads(
    uint32_t stb, int k0, int tid, int n0,
    const __nv_bfloat16* a_hi, const __nv_bfloat16* a_lo,
    const __nv_bfloat16* f_hi, const __nv_bfloat16* f_lo)
{
    // 2048 16B chunks: arr (4) x row (128) x seg (4); thread does 8,
    // arr = i>>1 resolved at compile time under full unroll.
    #pragma unroll
    for (int i = 0; i < 8; i++) {
        const __nv_bfloat16* base = (i < 2) ? a_hi : (i < 4) ? a_lo
                                  : (i < 6) ? f_hi : f_lo;
        const int arr = i >> 1;
        int rem = tid + 256 * (i & 1);       // < 512
        int row = rem >> 2;                  // 0..127
        int seg = tid & 3;                   // 0..3
        uint32_t daddr = stb + arr * ARR_BYTES + row * ROW_B + seg * 16;
        const void* gp = base + (size_t)row * D_SZ + k0 + seg * 8;
        int nbytes = (arr < 2 || (n0 + row) < N_SZ) ? 16 : 0;  // 0 => zero-fill
        CP_ASYNC_16(daddr, gp, nbytes);
    }
    CP_ASYNC_COMMIT();
}

__global__ __launch_bounds__(256, 1)
void mma_gemm_kernel(float* __restrict__ C) {
    extern __shared__ char smem[];
    const uint32_t sb = smem_u32(smem);
    const int tid  = threadIdx.x;
    const int lane = tid & 31;
    const int wid  = tid >> 5;
    const int warp_m = wid & 1;     // 2 warps over M
    const int warp_n = wid >> 1;    // 4 warps over N

    const int m0 = blockIdx.x * 128;
    const int n0 = blockIdx.y * 128;

    const __nv_bfloat16* a_hi = g_Ahi + (size_t)m0 * D_SZ;
    const __nv_bfloat16* a_lo = g_Alo + (size_t)m0 * D_SZ;
    const __nv_bfloat16* f_hi = g_Fhi + (size_t)n0 * D_SZ;
    const __nv_bfloat16* f_lo = g_Flo + (size_t)n0 * D_SZ;

    float acc[4][4][4];
    #pragma unroll
    for (int mi = 0; mi < 4; mi++)
        #pragma unroll
        for (int nj = 0; nj < 4; nj++)
            #pragma unroll
            for (int r = 0; r < 4; r++)
                acc[mi][nj][r] = 0.0f;

    // ldmatrix per-lane byte offsets inside an array tile
    // A (16x16 frag): row = frag_m + (lane&15), col-half = lane>>4
    //   -> regs r0..r3 = exact m16n8k16 A fragment order
    uint32_t a_off[4];
    #pragma unroll
    for (int i = 0; i < 4; i++)
        a_off[i] = (uint32_t)((warp_m * 64 + i * 16 + (lane & 15)) * ROW_B
                              + (lane >> 4) * 16);
    // B non-trans x4 covering 16 n-rows x k16: mat = lane>>3
    //   mat0 = n 0-7 @ k0-7, mat1 = n 0-7 @ k8-15, mat2/3 = n 8-15
    //   -> {r0,r1} = B-frag for first 8 n, {r2,r3} = next 8 n
    uint32_t b_off[2];
    {
        int mat = lane >> 3, r = lane & 7;
        #pragma unroll
        for (int j = 0; j < 2; j++)
            b_off[j] = (uint32_t)((warp_n * 32 + j * 16 + ((mat >> 1) << 3) + r) * ROW_B
                                  + ((mat & 1) << 4));
    }

    const int NK = D_SZ / BK;   // 64
    issue_tile_loads(sb, 0, tid, n0, a_hi, a_lo, f_hi, f_lo);

    for (int c = 0; c < NK; c++) {
        CP_ASYNC_WAIT_ALL();
        __syncthreads();
        if (c + 1 < NK)
            issue_tile_loads(sb + ((c + 1) & 1) * STAGE_BYTES, (c + 1) * BK,
                             tid, n0, a_hi, a_lo, f_hi, f_lo);

        const uint32_t stb = sb + (c & 1) * STAGE_BYTES;
        #pragma unroll
        for (int ks = 0; ks < 2; ks++) {
            uint32_t ah[4][4], al[4][4], bh[4][2], bl[4][2];
            #pragma unroll
            for (int i = 0; i < 4; i++) {
                LDSM_X4(ah[i], stb + 0 * ARR_BYTES + a_off[i] + ks * 32);
                LDSM_X4(al[i], stb + 1 * ARR_BYTES + a_off[i] + ks * 32);
            }
            #pragma unroll
            for (int j = 0; j < 2; j++) {
                uint32_t t[4];
                LDSM_X4(t, stb + 2 * ARR_BYTES + b_off[j] + ks * 32);
                bh[2*j][0] = t[0]; bh[2*j][1] = t[1];
                bh[2*j+1][0] = t[2]; bh[2*j+1][1] = t[3];
                LDSM_X4(t, stb + 3 * ARR_BYTES + b_off[j] + ks * 32);
                bl[2*j][0] = t[0]; bl[2*j][1] = t[1];
                bl[2*j+1][0] = t[2]; bl[2*j+1][1] = t[3];
            }
            #pragma unroll
            for (int mi = 0; mi < 4; mi++)
                #pragma unroll
                for (int nj = 0; nj < 4; nj++)
                    MMA_BF16(acc[mi][nj], ah[mi], bh[nj]);
            #pragma unroll
            for (int mi = 0; mi < 4; mi++)
                #pragma unroll
                for (int nj = 0; nj < 4; nj++)
                    MMA_BF16(acc[mi][nj], ah[mi], bl[nj]);
            #pragma unroll
            for (int mi = 0; mi < 4; mi++)
                #pragma unroll
                for (int nj = 0; nj < 4; nj++)
                    MMA_BF16(acc[mi][nj], al[mi], bh[nj]);
        }
        __syncthreads();
    }

    // Epilogue: m16n8 accum mapping: row = lane>>2 (+8 for c2,c3),
    // col = (lane&3)*2 (+1) -> two float2 stores per fragment.
    const int r0 = m0 + warp_m * 64 + (lane >> 2);
    const int c0 = n0 + warp_n * 32 + (lane & 3) * 2;
    #pragma unroll
    for (int mi = 0; mi < 4; mi++) {
        #pragma unroll
        for (int nj = 0; nj < 4; nj++) {
            int col = c0 + nj * 8;
            if (col < N_SZ) {   // col even, N even -> pair fully in-bounds
                float2 v01 = make_float2(acc[mi][nj][0], acc[mi][nj][1]);
                float2 v23 = make_float2(acc[mi][nj][2], acc[mi][nj][3]);
                *reinterpret_cast<float2*>(
                    C + (size_t)(r0 + mi * 16) * N_SZ + col) = v01;
                *reinterpret_cast<float2*>(
                    C + (size_t)(r0 + mi * 16 + 8) * N_SZ + col) = v23;
            }
        }
    }
}

// ---------------------------------------------------------------------------
// Memory-bank update kernels (unchanged; ~71us, DRAM-bound)
// ---------------------------------------------------------------------------
__global__ void init_winner_kernel() {
    int i = blockIdx.x * blockDim.x + threadIdx.x;
    if (i < N_SZ) g_winner[i] = -2;
}

__global__ void mark_kernel(const int* __restrict__ indexes,
                            const int* __restrict__ update_flag) {
    int i = blockIdx.x * blockDim.x + threadIdx.x;
    if (i < B_SZ) {
        int y = indexes[i];
        int v = (update_flag[i] > 0) ? i : -1;
        if (y >= 0 && y < N_SZ) atomicMax(&g_winner[y], v);
    }
}

__global__ void update_rows_kernel(const float* __restrict__ inputs,
                                   const float* __restrict__ feats,
                                   float* __restrict__ out_feats) {
    int y = blockIdx.x;
    int t = threadIdx.x;
    int w = g_winner[y];

    const float* src = (w >= 0) ? (inputs + (size_t)w * D_SZ)
                                : (feats  + (size_t)y * D_SZ);
    float* dst = out_feats + (size_t)y * D_SZ;

    float4 v0 = *reinterpret_cast<const float4*>(src + t * 4);
    float4 v1 = *reinterpret_cast<const float4*>(src + 1024 + t * 4);

    if (w == -2) {
        *reinterpret_cast<float4*>(dst + t * 4)        = v0;
        *reinterpret_cast<float4*>(dst + 1024 + t * 4) = v1;
        return;
    }

    float ss = v0.x * v0.x + v0.y * v0.y + v0.z * v0.z + v0.w * v0.w
             + v1.x * v1.x + v1.y * v1.y + v1.z * v1.z + v1.w * v1.w;
    #pragma unroll
    for (int o = 16; o > 0; o >>= 1)
        ss += __shfl_xor_sync(0xffffffffu, ss, o);

    __shared__ float sred[8];
    __shared__ float stot;
    if ((t & 31) == 0) sred[t >> 5] = ss;
    __syncthreads();
    if (t < 8) {
        float v = sred[t];
        v += __shfl_xor_sync(0x000000ffu, v, 4);
        v += __shfl_xor_sync(0x000000ffu, v, 2);
        v += __shfl_xor_sync(0x000000ffu, v, 1);
        if (t == 0) stot = v;
    }
    __syncthreads();

    float inv = 1.0f / fmaxf(sqrtf(stot), 1e-12f);
    v0.x *= inv; v0.y *= inv; v0.z *= inv; v0.w *= inv;
    v1.x *= inv; v1.y *= inv; v1.z *= inv; v1.w *= inv;
    *reinterpret_cast<float4*>(dst + t * 4)        = v0;
    *reinterpret_cast<float4*>(dst + 1024 + t * 4) = v1;
}

// ---------------------------------------------------------------------------
// Launch. Inputs: inputs f32[B,D], features f32[N,D], IoU f32[B] (unused),
// indexes int32[B], update_flag int32[B].
// Output: concat( outputs f32[B,N], new_features f32[N,D] ).
// ---------------------------------------------------------------------------
extern "C" void kernel_launch(void* const* d_in, const int* in_sizes, int n_in,
                              void* d_out, int out_size) {
    const float* inputs      = (const float*)d_in[0];
    const float* features    = (const float*)d_in[1];
    const int*   indexes     = (const int*)d_in[3];
    const int*   update_flag = (const int*)d_in[4];

    float* out       = (float*)d_out;                 // [B, N]
    float* out_feats = out + (size_t)B_SZ * N_SZ;     // [N, D]

    cudaFuncSetAttribute(mma_gemm_kernel,
                         cudaFuncAttributeMaxDynamicSharedMemorySize, SMEM_DYN);

    // 1) bf16 hi/lo split of A and F
    {
        size_t total4 = ((size_t)B_SZ * D_SZ + (size_t)N_SZ * D_SZ) / 4;
        int blocks = (int)((total4 + 255) / 256);
        convert_split_kernel<<<blocks, 256>>>(inputs, features);
    }

    // 2) tensor-core (HMMA) GEMM — dominant
    {
        dim3 grid(B_SZ / 128, (N_SZ + 127) / 128);   // (8, 235), m fastest
        mma_gemm_kernel<<<grid, 256, SMEM_DYN>>>(out);
    }

    // 3) memory-bank update
    init_winner_kernel<<<(N_SZ + 255) / 256, 256>>>();
    mark_kernel<<<(B_SZ + 255) / 256, 256>>>(indexes, update_flag);
    update_rows_kernel<<<N_SZ, 256>>>(inputs, features, out_feats);
}

// round 15
// speedup vs baseline: 3.7948x; 1.6344x over previous
#include <cuda_runtime.h>
#include <cuda_bf16.h>
#include <math.h>
#include <stdint.h>

// Problem dims (fixed by the reference)
#define B_SZ 1024
#define D_SZ 2048
#define N_SZ 30000

// ---------------------------------------------------------------------------
// Scratch
// ---------------------------------------------------------------------------
__device__ int g_winner[N_SZ];

// ---------------------------------------------------------------------------
// PTX helpers — base-sm_103-legal only (sm_80-era): mma.sync tf32, ldmatrix,
// cp.async. (tcgen05 rejected by this toolchain's base-sm_103 ptxas target.)
// ---------------------------------------------------------------------------
__device__ __forceinline__ uint32_t smem_u32(const void* p) {
    uint32_t a;
    asm("{ .reg .u64 t; cvta.to.shared.u64 t, %1; cvt.u32.u64 %0, t; }"
        : "=r"(a) : "l"(p));
    return a;
}

#define LDSM_X4(r, addr) \
    asm volatile("ldmatrix.sync.aligned.m8n8.x4.shared.b16 {%0,%1,%2,%3}, [%4];" \
        : "=r"((r)[0]), "=r"((r)[1]), "=r"((r)[2]), "=r"((r)[3]) : "r"(addr))

// round-to-nearest fp32 -> tf32 in-register (unbiased; HW truncation is not)
#define CVT_TF32(x) asm volatile("cvt.rna.tf32.f32 %0, %0;" : "+r"(x))

#define MMA_TF32(d, a, b) \
    asm volatile("mma.sync.aligned.m16n8k8.row.col.f32.tf32.tf32.f32 " \
        "{%0,%1,%2,%3}, {%4,%5,%6,%7}, {%8,%9}, {%0,%1,%2,%3};" \
        : "+f"((d)[0]), "+f"((d)[1]), "+f"((d)[2]), "+f"((d)[3]) \
        : "r"((a)[0]), "r"((a)[1]), "r"((a)[2]), "r"((a)[3]), \
          "r"((b)[0]), "r"((b)[1]))

#define CP_ASYNC_16(daddr, gptr, nbytes) \
    asm volatile("cp.async.cg.shared.global [%0], [%1], 16, %2;" \
        :: "r"(daddr), "l"(gptr), "r"(nbytes) : "memory")
#define CP_ASYNC_COMMIT() asm volatile("cp.async.commit_group;" ::: "memory")
#define CP_ASYNC_WAIT_2() asm volatile("cp.async.wait_group 2;" ::: "memory")

// ---------------------------------------------------------------------------
// TF32 HMMA GEMM:  C[m][n] = sum_k A[m][k] * F[n][k], single pass.
// Tile 128x128, BK=32 (fp32), 256 threads = 8 warps (2M x 4N), warp tile
// 64x32, m16n8k8 fragments loaded via the ldmatrix-as-8x4-fp32 trick.
// 3-stage cp.async pipeline, always-commit + wait_group 2.
// SMEM per stage: 2 arrays (A,F) x [128 rows][36 floats] (144B row pad:
// ldmatrix row addrs start at word 4r mod 32 -> 8 distinct 4-word spans).
// ---------------------------------------------------------------------------
#define BK 32
#define ROW_B 144
#define ARR_BYTES (128 * ROW_B)          // 18432
#define STAGE_BYTES (2 * ARR_BYTES)      // 36864
#define N_STAGE 3
#define SMEM_DYN (N_STAGE * STAGE_BYTES) // 110592

__device__ __forceinline__ void issue_tile_loads(
    uint32_t stb, int k0, int tid, int n0,
    const float* __restrict__ A, const float* __restrict__ F)
{
    // 2048 16B chunks: arr (2) x row (128) x seg (8); thread does 8.
    #pragma unroll
    for (int i = 0; i < 8; i++) {
        const int arr = i >> 2;                    // 0 = A, 1 = F
        const float* base = arr ? F : A;
        int rem = (i & 3) * 256 + tid;             // 0..1023
        int row = rem >> 3;                        // 0..127
        int seg = rem & 7;                         // 0..7 (16B = 4 floats)
        uint32_t daddr = stb + arr * ARR_BYTES + row * ROW_B + seg * 16;
        const void* gp = base + (size_t)row * D_SZ + k0 + seg * 4;
        int nbytes = (arr == 0 || (n0 + row) < N_SZ) ? 16 : 0;  // 0 => zero-fill
        CP_ASYNC_16(daddr, gp, nbytes);
    }
    CP_ASYNC_COMMIT();
}

__global__ __launch_bounds__(256, 1)
void mma_gemm_kernel(const float* __restrict__ A_g,
                     const float* __restrict__ F_g,
                     float* __restrict__ C) {
    extern __shared__ char smem[];
    const uint32_t sb = smem_u32(smem);
    const int tid  = threadIdx.x;
    const int lane = tid & 31;
    const int wid  = tid >> 5;
    const int warp_m = wid & 1;     // 2 warps over M
    const int warp_n = wid >> 1;    // 4 warps over N

    const int m0 = blockIdx.x * 128;
    const int n0 = blockIdx.y * 128;

    const float* A = A_g + (size_t)m0 * D_SZ;
    const float* F = F_g + (size_t)n0 * D_SZ;

    float acc[4][4][4];
    #pragma unroll
    for (int mi = 0; mi < 4; mi++)
        #pragma unroll
        for (int nj = 0; nj < 4; nj++)
            #pragma unroll
            for (int r = 0; r < 4; r++)
                acc[mi][nj][r] = 0.0f;

    // ldmatrix lane addressing (mat = lane>>3, r = lane&7), byte offsets:
    // A x4 frag (m16 x k8 as 4 8x4-fp32 mats): mat0={m0-7,k0-3} mat1={m8-15,k0-3}
    //   mat2={m0-7,k4-7} mat3={m8-15,k4-7} -> regs exactly a0..a3 of m16n8k8.
    const int mat = lane >> 3, mr = lane & 7;
    uint32_t a_off[4];
    #pragma unroll
    for (int mi = 0; mi < 4; mi++)
        a_off[mi] = (uint32_t)((warp_m * 64 + mi * 16 + (mat & 1) * 8 + mr) * ROW_B
                               + (mat >> 1) * 16);
    // B x4 covering 16 n rows (2 n-frags): mat0={n0-7,k0-3} mat1={n0-7,k4-7}
    //   mat2={n8-15,k0-3} mat3={n8-15,k4-7} -> {r0,r1}=frag 2j, {r2,r3}=frag 2j+1.
    uint32_t b_off[2];
    #pragma unroll
    for (int j = 0; j < 2; j++)
        b_off[j] = (uint32_t)((warp_n * 32 + j * 16 + (mat >> 1) * 8 + mr) * ROW_B
                              + (mat & 1) * 16);

    const int NK = D_SZ / BK;   // 64

    issue_tile_loads(sb + 0 * STAGE_BYTES, 0 * BK, tid, n0, A, F);
    issue_tile_loads(sb + 1 * STAGE_BYTES, 1 * BK, tid, n0, A, F);

    for (int c = 0; c < NK; c++) {
        // always commit (possibly-empty group) so wait_group 2 pins stage c
        if (c + 2 < NK)
            issue_tile_loads(sb + ((c + 2) % N_STAGE) * STAGE_BYTES,
                             (c + 2) * BK, tid, n0, A, F);
        else
            CP_ASYNC_COMMIT();
        CP_ASYNC_WAIT_2();
        __syncthreads();

        const uint32_t stb = sb + (c % N_STAGE) * STAGE_BYTES;
        #pragma unroll
        for (int ks = 0; ks < 4; ks++) {          // 4 x k8 per BK=32
            uint32_t a[4][4], b[4][2];
            #pragma unroll
            for (int mi = 0; mi < 4; mi++) {
                LDSM_X4(a[mi], stb + a_off[mi] + ks * 32);
                CVT_TF32(a[mi][0]); CVT_TF32(a[mi][1]);
                CVT_TF32(a[mi][2]); CVT_TF32(a[mi][3]);
            }
            #pragma unroll
            for (int j = 0; j < 2; j++) {
                uint32_t t[4];
                LDSM_X4(t, stb + ARR_BYTES + b_off[j] + ks * 32);
                CVT_TF32(t[0]); CVT_TF32(t[1]); CVT_TF32(t[2]); CVT_TF32(t[3]);
                b[2*j][0] = t[0]; b[2*j][1] = t[1];
                b[2*j+1][0] = t[2]; b[2*j+1][1] = t[3];
            }
            #pragma unroll
            for (int mi = 0; mi < 4; mi++)
                #pragma unroll
                for (int nj = 0; nj < 4; nj++)
                    MMA_TF32(acc[mi][nj], a[mi], b[nj]);
        }
        __syncthreads();   // all warps done with stage c before it is refilled
    }

    // Epilogue: m16n8 accum: row = lane>>2 (+8 for c2,c3), col = 2*(lane&3).
    const int r0 = m0 + warp_m * 64 + (lane >> 2);
    const int c0 = n0 + warp_n * 32 + (lane & 3) * 2;
    #pragma unroll
    for (int mi = 0; mi < 4; mi++) {
        #pragma unroll
        for (int nj = 0; nj < 4; nj++) {
            int col = c0 + nj * 8;
            if (col < N_SZ) {   // col even, N even -> pair fully in-bounds
                float2 v01 = make_float2(acc[mi][nj][0], acc[mi][nj][1]);
                float2 v23 = make_float2(acc[mi][nj][2], acc[mi][nj][3]);
                *reinterpret_cast<float2*>(
                    C + (size_t)(r0 + mi * 16) * N_SZ + col) = v01;
                *reinterpret_cast<float2*>(
                    C + (size_t)(r0 + mi * 16 + 8) * N_SZ + col) = v23;
            }
        }
    }
}

// ---------------------------------------------------------------------------
// Memory-bank update kernels (unchanged; ~71us, DRAM-bound)
// ---------------------------------------------------------------------------
__global__ void init_winner_kernel() {
    int i = blockIdx.x * blockDim.x + threadIdx.x;
    if (i < N_SZ) g_winner[i] = -2;
}

__global__ void mark_kernel(const int* __restrict__ indexes,
                            const int* __restrict__ update_flag) {
    int i = blockIdx.x * blockDim.x + threadIdx.x;
    if (i < B_SZ) {
        int y = indexes[i];
        int v = (update_flag[i] > 0) ? i : -1;
        if (y >= 0 && y < N_SZ) atomicMax(&g_winner[y], v);
    }
}

__global__ void update_rows_kernel(const float* __restrict__ inputs,
                                   const float* __restrict__ feats,
                                   float* __restrict__ out_feats) {
    int y = blockIdx.x;
    int t = threadIdx.x;
    int w = g_winner[y];

    const float* src = (w >= 0) ? (inputs + (size_t)w * D_SZ)
                                : (feats  + (size_t)y * D_SZ);
    float* dst = out_feats + (size_t)y * D_SZ;

    float4 v0 = *reinterpret_cast<const float4*>(src + t * 4);
    float4 v1 = *reinterpret_cast<const float4*>(src + 1024 + t * 4);

    if (w == -2) {
        *reinterpret_cast<float4*>(dst + t * 4)        = v0;
        *reinterpret_cast<float4*>(dst + 1024 + t * 4) = v1;
        return;
    }

    float ss = v0.x * v0.x + v0.y * v0.y + v0.z * v0.z + v0.w * v0.w
             + v1.x * v1.x + v1.y * v1.y + v1.z * v1.z + v1.w * v1.w;
    #pragma unroll
    for (int o = 16; o > 0; o >>= 1)
        ss += __shfl_xor_sync(0xffffffffu, ss, o);

    __shared__ float sred[8];
    __shared__ float stot;
    if ((t & 31) == 0) sred[t >> 5] = ss;
    __syncthreads();
    if (t < 8) {
        float v = sred[t];
        v += __shfl_xor_sync(0x000000ffu, v, 4);
        v += __shfl_xor_sync(0x000000ffu, v, 2);
        v += __shfl_xor_sync(0x000000ffu, v, 1);
        if (t == 0) stot = v;
    }
    __syncthreads();

    float inv = 1.0f / fmaxf(sqrtf(stot), 1e-12f);
    v0.x *= inv; v0.y *= inv; v0.z *= inv; v0.w *= inv;
    v1.x *= inv; v1.y *= inv; v1.z *= inv; v1.w *= inv;
    *reinterpret_cast<float4*>(dst + t * 4)        = v0;
    *reinterpret_cast<float4*>(dst + 1024 + t * 4) = v1;
}

// ---------------------------------------------------------------------------
// Launch. Inputs: inputs f32[B,D], features f32[N,D], IoU f32[B] (unused),
// indexes int32[B], update_flag int32[B].
// Output: concat( outputs f32[B,N], new_features f32[N,D] ).
// ---------------------------------------------------------------------------
extern "C" void kernel_launch(void* const* d_in, const int* in_sizes, int n_in,
                              void* d_out, int out_size) {
    const float* inputs      = (const float*)d_in[0];
    const float* features    = (const float*)d_in[1];
    const int*   indexes     = (const int*)d_in[3];
    const int*   update_flag = (const int*)d_in[4];

    float* out       = (float*)d_out;                 // [B, N]
    float* out_feats = out + (size_t)B_SZ * N_SZ;     // [N, D]

    cudaFuncSetAttribute(mma_gemm_kernel,
                         cudaFuncAttributeMaxDynamicSharedMemorySize, SMEM_DYN);

    // 1) TF32 tensor-core GEMM — dominant (reads fp32 inputs directly)
    {
        dim3 grid(B_SZ / 128, (N_SZ + 127) / 128);   // (8, 235), m fastest
        mma_gemm_kernel<<<grid, 256, SMEM_DYN>>>(inputs, features, out);
    }

    // 2) memory-bank update
    init_winner_kernel<<<(N_SZ + 255) / 256, 256>>>();
    mark_kernel<<<(B_SZ + 255) / 256, 256>>>(indexes, update_flag);
    update_rows_kernel<<<N_SZ, 256>>>(inputs, features, out_feats);
}